// round 1
// baseline (speedup 1.0000x reference)
#include <cuda_runtime.h>
#include <cstdint>

#define BB 2
#define LL 2048
#define DM 1024
#define DI 2048
#define DS 16
#define BL (BB*LL)   /* 4096 tokens */

// ---------------- scratch (no allocations allowed) ----------------
__device__ float g_xn[(size_t)BL * DM];        // 16 MB  layernorm out
__device__ float g_xz[(size_t)BL * 2 * DI];    // 64 MB  in-proj out (x_branch | z)
__device__ float g_xb[(size_t)BL * DI];        // 32 MB  conv+silu out
__device__ float g_bc[(size_t)BL * 2 * DS];    // 0.5 MB B|C
__device__ float g_dt[(size_t)BL * DI];        // 32 MB  softplus(dt)
__device__ float g_y [(size_t)BL * DI];        // 32 MB  scan out * silu(z)

__device__ __forceinline__ float warp_sum(float v) {
    #pragma unroll
    for (int o = 16; o > 0; o >>= 1) v += __shfl_xor_sync(0xffffffffu, v, o);
    return v;
}

// ---------------- LayerNorm ----------------
__global__ __launch_bounds__(256) void ln_kernel(const float* __restrict__ x,
                                                 const float* __restrict__ g,
                                                 const float* __restrict__ b) {
    int t = blockIdx.x;
    int tid = threadIdx.x;
    const float4* row = (const float4*)(x + (size_t)t * DM);
    float4 v = row[tid];
    float s  = v.x + v.y + v.z + v.w;
    float sq = v.x*v.x + v.y*v.y + v.z*v.z + v.w*v.w;
    __shared__ float red[16];
    __shared__ float stats[2];
    s = warp_sum(s); sq = warp_sum(sq);
    int wid = tid >> 5, lid = tid & 31;
    if (lid == 0) { red[wid] = s; red[8 + wid] = sq; }
    __syncthreads();
    if (tid < 32) {
        float ss = (tid < 8) ? red[tid] : 0.f;
        float qq = (tid < 8) ? red[8 + tid] : 0.f;
        ss = warp_sum(ss); qq = warp_sum(qq);
        if (tid == 0) {
            float mu = ss * (1.f / DM);
            float var = qq * (1.f / DM) - mu * mu;
            stats[0] = mu;
            stats[1] = rsqrtf(var + 1e-5f);
        }
    }
    __syncthreads();
    float mu = stats[0], rstd = stats[1];
    float4 gg = ((const float4*)g)[tid];
    float4 bb = ((const float4*)b)[tid];
    float4 o;
    o.x = (v.x - mu) * rstd * gg.x + bb.x;
    o.y = (v.y - mu) * rstd * gg.y + bb.y;
    o.z = (v.z - mu) * rstd * gg.z + bb.z;
    o.w = (v.w - mu) * rstd * gg.w + bb.w;
    ((float4*)(g_xn + (size_t)t * DM))[tid] = o;
}

// ---------------- Generic C = A * B^T GEMM (both K-contiguous) ----------------
// MODE 0: plain store. MODE 1: softplus(v + bias[n]). MODE 2: v + res[m*N+n].
#define GBM 128
#define GBN 128
#define GBK 16

template<int MODE>
__global__ __launch_bounds__(256) void gemm_tn(const float* __restrict__ A,
                                               const float* __restrict__ B,
                                               float* __restrict__ C,
                                               int M, int N, int K,
                                               const float* __restrict__ extra) {
    __shared__ float sA[GBK][GBM + 4];
    __shared__ float sB[GBK][GBN + 4];
    int tid = threadIdx.x;
    int tx = tid & 15, ty = tid >> 4;
    int m0 = blockIdx.y * GBM;
    int n0 = blockIdx.x * GBN;

    float acc[8][8];
    #pragma unroll
    for (int i = 0; i < 8; i++)
        #pragma unroll
        for (int j = 0; j < 8; j++) acc[i][j] = 0.f;

    for (int k0 = 0; k0 < K; k0 += GBK) {
        #pragma unroll
        for (int i = 0; i < 2; i++) {
            int linear = tid + i * 256;
            int row = linear >> 2;
            int kq  = (linear & 3) << 2;
            float4 va = *(const float4*)(A + (size_t)(m0 + row) * K + k0 + kq);
            sA[kq + 0][row] = va.x; sA[kq + 1][row] = va.y;
            sA[kq + 2][row] = va.z; sA[kq + 3][row] = va.w;
            float4 vb = *(const float4*)(B + (size_t)(n0 + row) * K + k0 + kq);
            sB[kq + 0][row] = vb.x; sB[kq + 1][row] = vb.y;
            sB[kq + 2][row] = vb.z; sB[kq + 3][row] = vb.w;
        }
        __syncthreads();
        #pragma unroll
        for (int kk = 0; kk < GBK; kk++) {
            float a[8], b[8];
            *(float4*)(a)     = *(const float4*)&sA[kk][ty * 8];
            *(float4*)(a + 4) = *(const float4*)&sA[kk][ty * 8 + 4];
            *(float4*)(b)     = *(const float4*)&sB[kk][tx * 8];
            *(float4*)(b + 4) = *(const float4*)&sB[kk][tx * 8 + 4];
            #pragma unroll
            for (int i = 0; i < 8; i++)
                #pragma unroll
                for (int j = 0; j < 8; j++)
                    acc[i][j] += a[i] * b[j];
        }
        __syncthreads();
    }

    #pragma unroll
    for (int i = 0; i < 8; i++) {
        int m = m0 + ty * 8 + i;
        #pragma unroll
        for (int j = 0; j < 8; j++) {
            int n = n0 + tx * 8 + j;
            float v = acc[i][j];
            if (MODE == 1) {
                v += extra[n];
                v = (v > 20.f) ? v : log1pf(__expf(v));
            } else if (MODE == 2) {
                v += extra[(size_t)m * N + n];
            }
            C[(size_t)m * N + n] = v;
        }
    }
}

// ---------------- causal depthwise conv (k=4) + bias + SiLU ----------------
__global__ __launch_bounds__(256) void conv_silu_kernel(const float* __restrict__ cw,
                                                        const float* __restrict__ cb) {
    int idx = blockIdx.x * blockDim.x + threadIdx.x;   // over BL*DI
    if (idx >= BL * DI) return;
    int d = idx & (DI - 1);
    int t = idx >> 11;              // b*L + l
    int l = t & (LL - 1);
    int bb = t >> 11;
    float w0 = cw[d * 4 + 0], w1 = cw[d * 4 + 1];
    float w2 = cw[d * 4 + 2], w3 = cw[d * 4 + 3];
    const float* base = g_xz + ((size_t)(bb << 11)) * (2 * DI) + d;
    float acc = cb[d];
    if (l >= 3) acc += w0 * base[(size_t)(l - 3) * (2 * DI)];
    if (l >= 2) acc += w1 * base[(size_t)(l - 2) * (2 * DI)];
    if (l >= 1) acc += w2 * base[(size_t)(l - 1) * (2 * DI)];
    acc += w3 * base[(size_t)l * (2 * DI)];
    float s = acc / (1.f + __expf(-acc));              // silu
    g_xb[idx] = s;
}

// ---------------- B/C projection: bc[t,n] = dot(xb[t,:], W_x[n,:]) ----------------
__global__ __launch_bounds__(256) void xdbl_kernel(const float* __restrict__ Wx) {
    int gw = (blockIdx.x * blockDim.x + threadIdx.x) >> 5;   // global warp
    int lane = threadIdx.x & 31;
    int t = gw >> 5;                 // token
    int n = gw & 31;                 // output channel 0..31
    const float4* x4 = (const float4*)(g_xb + (size_t)t * DI);
    const float4* w4 = (const float4*)(Wx + (size_t)n * DI);
    float s = 0.f;
    #pragma unroll
    for (int i = 0; i < DI / 4 / 32; i++) {
        float4 a = x4[lane + i * 32];
        float4 b = w4[lane + i * 32];
        s += a.x * b.x + a.y * b.y + a.z * b.z + a.w * b.w;
    }
    s = warp_sum(s);
    if (lane == 0) g_bc[(size_t)t * 32 + n] = s;
}

// ---------------- selective scan (1 thread per (b,d), 16 states in regs) ----------------
__global__ __launch_bounds__(128) void scan_kernel(const float* __restrict__ A_log,
                                                   const float* __restrict__ Dp) {
    int tid = blockIdx.x * 128 + threadIdx.x;   // 0..4095
    int d  = tid & (DI - 1);
    int bb = tid >> 11;

    float Aa[16];
    #pragma unroll
    for (int n = 0; n < 16; n++) Aa[n] = -__expf(A_log[(size_t)d * DS + n]);
    float dpv = Dp[d];

    float h[16];
    #pragma unroll
    for (int n = 0; n < 16; n++) h[n] = 0.f;

    const float* dt_p = g_dt + (size_t)bb * LL * DI + d;
    const float* xb_p = g_xb + (size_t)bb * LL * DI + d;
    const float* z_p  = g_xz + (size_t)bb * LL * (2 * DI) + DI + d;
    const float4* bc4 = (const float4*)(g_bc + (size_t)bb * LL * 32);
    float* y_p = g_y + (size_t)bb * LL * DI + d;

    for (int l = 0; l < LL; l++) {
        float dtv = dt_p[(size_t)l * DI];
        float xv  = xb_p[(size_t)l * DI];
        float Bv[16], Cv[16];
        *(float4*)&Bv[0]  = bc4[l * 8 + 0];
        *(float4*)&Bv[4]  = bc4[l * 8 + 1];
        *(float4*)&Bv[8]  = bc4[l * 8 + 2];
        *(float4*)&Bv[12] = bc4[l * 8 + 3];
        *(float4*)&Cv[0]  = bc4[l * 8 + 4];
        *(float4*)&Cv[4]  = bc4[l * 8 + 5];
        *(float4*)&Cv[8]  = bc4[l * 8 + 6];
        *(float4*)&Cv[12] = bc4[l * 8 + 7];

        float dx = dtv * xv;
        float y = 0.f;
        #pragma unroll
        for (int n = 0; n < 16; n++) {
            float ab = __expf(dtv * Aa[n]);
            h[n] = ab * h[n] + dx * Bv[n];
            y += h[n] * Cv[n];
        }
        y += dpv * xv;
        float zv = z_p[(size_t)l * (2 * DI)];
        y *= zv / (1.f + __expf(-zv));
        y_p[(size_t)l * DI] = y;
    }
}

// ---------------- launch ----------------
extern "C" void kernel_launch(void* const* d_in, const int* in_sizes, int n_in,
                              void* d_out, int out_size) {
    const float* x      = (const float*)d_in[0];
    const float* W_in   = (const float*)d_in[1];
    const float* conv_w = (const float*)d_in[2];
    const float* conv_b = (const float*)d_in[3];
    const float* W_x    = (const float*)d_in[4];
    const float* W_dt   = (const float*)d_in[5];
    const float* b_dt   = (const float*)d_in[6];
    const float* A_log  = (const float*)d_in[7];
    const float* Dp     = (const float*)d_in[8];
    const float* W_out  = (const float*)d_in[9];
    const float* ln_g   = (const float*)d_in[10];
    const float* ln_b   = (const float*)d_in[11];
    float* out = (float*)d_out;

    float* xn = nullptr; float* xz = nullptr; float* xb = nullptr;
    float* dt = nullptr; float* yy = nullptr;
    cudaGetSymbolAddress((void**)&xn, g_xn);
    cudaGetSymbolAddress((void**)&xz, g_xz);
    cudaGetSymbolAddress((void**)&xb, g_xb);
    cudaGetSymbolAddress((void**)&dt, g_dt);
    cudaGetSymbolAddress((void**)&yy, g_y);

    // 1. LayerNorm
    ln_kernel<<<BL, 256>>>(x, ln_g, ln_b);

    // 2. in-projection: xz[t,e] = sum_d xn[t,d] * W_in[e,d]   (M=4096,N=4096,K=1024)
    gemm_tn<0><<<dim3((2 * DI) / GBN, BL / GBM), 256>>>(xn, W_in, xz, BL, 2 * DI, DM, nullptr);

    // 3. conv + silu -> g_xb
    conv_silu_kernel<<<(BL * DI) / 256, 256>>>(conv_w, conv_b);

    // 4. B/C projection -> g_bc
    xdbl_kernel<<<(BL * 32 * 32) / 256, 256>>>(W_x);

    // 5. dt GEMM + bias + softplus -> g_dt   (M=4096,N=2048,K=2048)
    gemm_tn<1><<<dim3(DI / GBN, BL / GBM), 256>>>(xb, W_dt, dt, BL, DI, DI, b_dt);

    // 6. selective scan + gating -> g_y
    scan_kernel<<<32, 128>>>(A_log, Dp);

    // 7. out-projection + residual   (M=4096,N=1024,K=2048)
    gemm_tn<2><<<dim3(DM / GBN, BL / GBM), 256>>>(yy, W_out, out, BL, DM, DI, x);
}

// round 2
// speedup vs baseline: 1.7118x; 1.7118x over previous
#include <cuda_runtime.h>
#include <cstdint>

#define BB 2
#define LL 2048
#define DM 1024
#define DI 2048
#define DS 16
#define BL (BB*LL)   /* 4096 tokens */
#define CH 16        /* scan chunks */
#define CL (LL/CH)   /* 128 steps per chunk */

typedef unsigned long long u64;

// ---------------- scratch (no allocations allowed) ----------------
__device__ float g_xn[(size_t)BL * DM];        // layernorm out
__device__ float g_xz[(size_t)BL * 2 * DI];    // in-proj out (x_branch | z)
__device__ float g_xb[(size_t)BL * DI];        // conv+silu out
__device__ float g_bc[(size_t)BL * 2 * DS];    // B|C
__device__ float g_dt[(size_t)BL * DI];        // softplus(dt)
__device__ float g_y [(size_t)BL * DI];        // scan out * silu(z)
__device__ float g_P [(size_t)BB * CH * DI * DS];  // chunk state decay
__device__ float g_S [(size_t)BB * CH * DI * DS];  // chunk local solution
__device__ float g_Hi[(size_t)BB * CH * DI * DS];  // chunk initial state

__device__ __forceinline__ float warp_sum(float v) {
    #pragma unroll
    for (int o = 16; o > 0; o >>= 1) v += __shfl_xor_sync(0xffffffffu, v, o);
    return v;
}

__device__ __forceinline__ u64 pack2(float x) {
    u64 r; asm("mov.b64 %0, {%1, %1};" : "=l"(r) : "f"(x)); return r;
}
__device__ __forceinline__ void fma2(u64& d, u64 a, u64 b) {
    asm("fma.rn.f32x2 %0, %1, %2, %3;" : "=l"(d) : "l"(a), "l"(b), "l"(d));
}
__device__ __forceinline__ void unpack2(float& lo, float& hi, u64 v) {
    asm("mov.b64 {%0, %1}, %2;" : "=f"(lo), "=f"(hi) : "l"(v));
}

// ---------------- LayerNorm ----------------
__global__ __launch_bounds__(256) void ln_kernel(const float* __restrict__ x,
                                                 const float* __restrict__ g,
                                                 const float* __restrict__ b) {
    int t = blockIdx.x;
    int tid = threadIdx.x;
    const float4* row = (const float4*)(x + (size_t)t * DM);
    float4 v = row[tid];
    float s  = v.x + v.y + v.z + v.w;
    float sq = v.x*v.x + v.y*v.y + v.z*v.z + v.w*v.w;
    __shared__ float red[16];
    __shared__ float stats[2];
    s = warp_sum(s); sq = warp_sum(sq);
    int wid = tid >> 5, lid = tid & 31;
    if (lid == 0) { red[wid] = s; red[8 + wid] = sq; }
    __syncthreads();
    if (tid < 32) {
        float ss = (tid < 8) ? red[tid] : 0.f;
        float qq = (tid < 8) ? red[8 + tid] : 0.f;
        ss = warp_sum(ss); qq = warp_sum(qq);
        if (tid == 0) {
            float mu = ss * (1.f / DM);
            float var = qq * (1.f / DM) - mu * mu;
            stats[0] = mu;
            stats[1] = rsqrtf(var + 1e-5f);
        }
    }
    __syncthreads();
    float mu = stats[0], rstd = stats[1];
    float4 gg = ((const float4*)g)[tid];
    float4 bb = ((const float4*)b)[tid];
    float4 o;
    o.x = (v.x - mu) * rstd * gg.x + bb.x;
    o.y = (v.y - mu) * rstd * gg.y + bb.y;
    o.z = (v.z - mu) * rstd * gg.z + bb.z;
    o.w = (v.w - mu) * rstd * gg.w + bb.w;
    ((float4*)(g_xn + (size_t)t * DM))[tid] = o;
}

// ---------------- C = A * B^T GEMM, f32x2 packed FMA ----------------
// MODE 0: plain. MODE 1: softplus(v + bias[n]). MODE 2: v + res[m*N+n].
#define GBM 128
#define GBN 128
#define GBK 16

template<int MODE>
__global__ __launch_bounds__(256) void gemm_tn(const float* __restrict__ A,
                                               const float* __restrict__ B,
                                               float* __restrict__ C,
                                               int M, int N, int K,
                                               const float* __restrict__ extra) {
    __shared__ __align__(16) float sA[GBK][GBM + 4];
    __shared__ __align__(16) float sB[GBK][GBN + 4];
    int tid = threadIdx.x;
    int tx = tid & 15, ty = tid >> 4;
    int m0 = blockIdx.y * GBM;
    int n0 = blockIdx.x * GBN;

    u64 acc[8][4];
    #pragma unroll
    for (int i = 0; i < 8; i++)
        #pragma unroll
        for (int j = 0; j < 4; j++) acc[i][j] = 0ull;

    // loader geometry: each thread loads rows r0 and r0+64 at k-quad kq0
    int r0  = tid >> 2;
    int kq0 = (tid & 3) << 2;
    const float* pa = A + (size_t)(m0 + r0) * K + kq0;
    const float* pb = B + (size_t)(n0 + r0) * K + kq0;
    size_t half = (size_t)64 * K;

    float4 ra0 = *(const float4*)(pa);
    float4 ra1 = *(const float4*)(pa + half);
    float4 rb0 = *(const float4*)(pb);
    float4 rb1 = *(const float4*)(pb + half);

    int nk = K / GBK;
    for (int kt = 0; kt < nk; kt++) {
        // commit staged regs to smem (transposed)
        sA[kq0 + 0][r0] = ra0.x; sA[kq0 + 1][r0] = ra0.y;
        sA[kq0 + 2][r0] = ra0.z; sA[kq0 + 3][r0] = ra0.w;
        sA[kq0 + 0][r0 + 64] = ra1.x; sA[kq0 + 1][r0 + 64] = ra1.y;
        sA[kq0 + 2][r0 + 64] = ra1.z; sA[kq0 + 3][r0 + 64] = ra1.w;
        sB[kq0 + 0][r0] = rb0.x; sB[kq0 + 1][r0] = rb0.y;
        sB[kq0 + 2][r0] = rb0.z; sB[kq0 + 3][r0] = rb0.w;
        sB[kq0 + 0][r0 + 64] = rb1.x; sB[kq0 + 1][r0 + 64] = rb1.y;
        sB[kq0 + 2][r0 + 64] = rb1.z; sB[kq0 + 3][r0 + 64] = rb1.w;
        __syncthreads();

        // prefetch next tile into regs (hidden under compute)
        if (kt + 1 < nk) {
            int ko = (kt + 1) * GBK;
            ra0 = *(const float4*)(pa + ko);
            ra1 = *(const float4*)(pa + half + ko);
            rb0 = *(const float4*)(pb + ko);
            rb1 = *(const float4*)(pb + half + ko);
        }

        #pragma unroll
        for (int kk = 0; kk < GBK; kk++) {
            float a[8];
            *(float4*)(a)     = *(const float4*)&sA[kk][ty * 8];
            *(float4*)(a + 4) = *(const float4*)&sA[kk][ty * 8 + 4];
            u64 b2[4];
            *(ulonglong2*)(b2)     = *(const ulonglong2*)&sB[kk][tx * 8];
            *(ulonglong2*)(b2 + 2) = *(const ulonglong2*)&sB[kk][tx * 8 + 4];
            u64 a2[8];
            #pragma unroll
            for (int i = 0; i < 8; i++) a2[i] = pack2(a[i]);
            #pragma unroll
            for (int i = 0; i < 8; i++)
                #pragma unroll
                for (int j = 0; j < 4; j++)
                    fma2(acc[i][j], a2[i], b2[j]);
        }
        __syncthreads();
    }

    #pragma unroll
    for (int i = 0; i < 8; i++) {
        int m = m0 + ty * 8 + i;
        float* crow = C + (size_t)m * N + n0 + tx * 8;
        #pragma unroll
        for (int j = 0; j < 4; j++) {
            float lo, hi;
            unpack2(lo, hi, acc[i][j]);
            if (MODE == 1) {
                lo += extra[n0 + tx * 8 + 2 * j];
                hi += extra[n0 + tx * 8 + 2 * j + 1];
                lo = (lo > 20.f) ? lo : log1pf(__expf(lo));
                hi = (hi > 20.f) ? hi : log1pf(__expf(hi));
            } else if (MODE == 2) {
                const float* r = extra + (size_t)m * N + n0 + tx * 8 + 2 * j;
                lo += r[0]; hi += r[1];
            }
            float2 v; v.x = lo; v.y = hi;
            *(float2*)(crow + 2 * j) = v;
        }
    }
}

// ---------------- causal depthwise conv (k=4) + bias + SiLU ----------------
__global__ __launch_bounds__(256) void conv_silu_kernel(const float* __restrict__ cw,
                                                        const float* __restrict__ cb) {
    int idx = blockIdx.x * blockDim.x + threadIdx.x;
    if (idx >= BL * DI) return;
    int d = idx & (DI - 1);
    int t = idx >> 11;
    int l = t & (LL - 1);
    int bb = t >> 11;
    float w0 = cw[d * 4 + 0], w1 = cw[d * 4 + 1];
    float w2 = cw[d * 4 + 2], w3 = cw[d * 4 + 3];
    const float* base = g_xz + ((size_t)(bb << 11)) * (2 * DI) + d;
    float acc = cb[d];
    if (l >= 3) acc += w0 * base[(size_t)(l - 3) * (2 * DI)];
    if (l >= 2) acc += w1 * base[(size_t)(l - 2) * (2 * DI)];
    if (l >= 1) acc += w2 * base[(size_t)(l - 1) * (2 * DI)];
    acc += w3 * base[(size_t)l * (2 * DI)];
    float s = acc / (1.f + __expf(-acc));
    g_xb[idx] = s;
}

// ---------------- B/C projection as tiled GEMM: 32 tokens x 32 outs ----------------
#define XT 32
__global__ __launch_bounds__(256) void xdbl_kernel(const float* __restrict__ Wx) {
    __shared__ __align__(16) float sX[16][XT + 4];
    __shared__ __align__(16) float sW[16][32 + 4];
    int tid = threadIdx.x;
    int t0 = blockIdx.x * XT;
    int tx = tid & 31;        // n
    int ty = tid >> 5;        // 0..7 token quads
    float acc[4] = {0.f, 0.f, 0.f, 0.f};

    for (int k0 = 0; k0 < DI; k0 += 16) {
        int row = (tid & 127) >> 2;
        int kq  = (tid & 3) << 2;
        if (tid < 128) {
            float4 v = *(const float4*)(g_xb + (size_t)(t0 + row) * DI + k0 + kq);
            sX[kq + 0][row] = v.x; sX[kq + 1][row] = v.y;
            sX[kq + 2][row] = v.z; sX[kq + 3][row] = v.w;
        } else {
            float4 v = *(const float4*)(Wx + (size_t)row * DI + k0 + kq);
            sW[kq + 0][row] = v.x; sW[kq + 1][row] = v.y;
            sW[kq + 2][row] = v.z; sW[kq + 3][row] = v.w;
        }
        __syncthreads();
        #pragma unroll
        for (int kk = 0; kk < 16; kk++) {
            float w = sW[kk][tx];
            float4 xv = *(const float4*)&sX[kk][ty * 4];
            acc[0] += xv.x * w; acc[1] += xv.y * w;
            acc[2] += xv.z * w; acc[3] += xv.w * w;
        }
        __syncthreads();
    }
    #pragma unroll
    for (int i = 0; i < 4; i++)
        g_bc[(size_t)(t0 + ty * 4 + i) * 32 + tx] = acc[i];
}

// ---------------- chunked selective scan ----------------
// Pass A: per (b,c,d) compute P = prod(A_bar), S = local h with h0=0
__global__ __launch_bounds__(256) void scanA_kernel(const float* __restrict__ A_log) {
    int id = blockIdx.x * 256 + threadIdx.x;   // BB*CH*DI
    int d = id & (DI - 1);
    int c = (id >> 11) & (CH - 1);
    int b = id >> 15;

    float Aa[16];
    #pragma unroll
    for (int n = 0; n < 16; n++) Aa[n] = -__expf(A_log[(size_t)d * DS + n]);

    float h[16], P[16];
    #pragma unroll
    for (int n = 0; n < 16; n++) { h[n] = 0.f; P[n] = 1.f; }

    int l0 = c * CL;
    const float* dt_p = g_dt + ((size_t)b * LL + l0) * DI + d;
    const float* xb_p = g_xb + ((size_t)b * LL + l0) * DI + d;
    const float4* bc4 = (const float4*)(g_bc + ((size_t)b * LL + l0) * 32);

    for (int l = 0; l < CL; l++) {
        float dtv = dt_p[(size_t)l * DI];
        float xv  = xb_p[(size_t)l * DI];
        float Bv[16];
        *(float4*)&Bv[0]  = bc4[l * 8 + 0];
        *(float4*)&Bv[4]  = bc4[l * 8 + 1];
        *(float4*)&Bv[8]  = bc4[l * 8 + 2];
        *(float4*)&Bv[12] = bc4[l * 8 + 3];
        float dx = dtv * xv;
        #pragma unroll
        for (int n = 0; n < 16; n++) {
            float ab = __expf(dtv * Aa[n]);
            h[n] = ab * h[n] + dx * Bv[n];
            P[n] *= ab;
        }
    }
    size_t base = (((size_t)b * CH + c) * DI + d) * DS;
    #pragma unroll
    for (int n = 0; n < 16; n += 4) {
        *(float4*)(g_S + base + n) = *(float4*)&h[n];
        *(float4*)(g_P + base + n) = *(float4*)&P[n];
    }
}

// Combine: sequential over chunks per (b,d); writes initial state per chunk
__global__ __launch_bounds__(256) void scanC_kernel() {
    int id = blockIdx.x * 256 + threadIdx.x;   // BB*DI
    int d = id & (DI - 1);
    int b = id >> 11;
    float h[16];
    #pragma unroll
    for (int n = 0; n < 16; n++) h[n] = 0.f;
    for (int c = 0; c < CH; c++) {
        size_t base = (((size_t)b * CH + c) * DI + d) * DS;
        #pragma unroll
        for (int n = 0; n < 16; n += 4)
            *(float4*)(g_Hi + base + n) = *(float4*)&h[n];
        float P[16], S[16];
        #pragma unroll
        for (int n = 0; n < 16; n += 4) {
            *(float4*)&P[n] = *(const float4*)(g_P + base + n);
            *(float4*)&S[n] = *(const float4*)(g_S + base + n);
        }
        #pragma unroll
        for (int n = 0; n < 16; n++) h[n] = P[n] * h[n] + S[n];
    }
}

// Pass B: replay chunk with correct h0, produce gated output
__global__ __launch_bounds__(256) void scanB_kernel(const float* __restrict__ A_log,
                                                    const float* __restrict__ Dp) {
    int id = blockIdx.x * 256 + threadIdx.x;
    int d = id & (DI - 1);
    int c = (id >> 11) & (CH - 1);
    int b = id >> 15;

    float Aa[16];
    #pragma unroll
    for (int n = 0; n < 16; n++) Aa[n] = -__expf(A_log[(size_t)d * DS + n]);
    float dpv = Dp[d];

    float h[16];
    size_t hbase = (((size_t)b * CH + c) * DI + d) * DS;
    #pragma unroll
    for (int n = 0; n < 16; n += 4)
        *(float4*)&h[n] = *(const float4*)(g_Hi + hbase + n);

    int l0 = c * CL;
    const float* dt_p = g_dt + ((size_t)b * LL + l0) * DI + d;
    const float* xb_p = g_xb + ((size_t)b * LL + l0) * DI + d;
    const float* z_p  = g_xz + ((size_t)b * LL + l0) * (2 * DI) + DI + d;
    const float4* bc4 = (const float4*)(g_bc + ((size_t)b * LL + l0) * 32);
    float* y_p = g_y + ((size_t)b * LL + l0) * DI + d;

    for (int l = 0; l < CL; l++) {
        float dtv = dt_p[(size_t)l * DI];
        float xv  = xb_p[(size_t)l * DI];
        float Bv[16], Cv[16];
        *(float4*)&Bv[0]  = bc4[l * 8 + 0];
        *(float4*)&Bv[4]  = bc4[l * 8 + 1];
        *(float4*)&Bv[8]  = bc4[l * 8 + 2];
        *(float4*)&Bv[12] = bc4[l * 8 + 3];
        *(float4*)&Cv[0]  = bc4[l * 8 + 4];
        *(float4*)&Cv[4]  = bc4[l * 8 + 5];
        *(float4*)&Cv[8]  = bc4[l * 8 + 6];
        *(float4*)&Cv[12] = bc4[l * 8 + 7];

        float dx = dtv * xv;
        float y = 0.f;
        #pragma unroll
        for (int n = 0; n < 16; n++) {
            float ab = __expf(dtv * Aa[n]);
            h[n] = ab * h[n] + dx * Bv[n];
            y += h[n] * Cv[n];
        }
        y += dpv * xv;
        float zv = z_p[(size_t)l * (2 * DI)];
        y *= zv / (1.f + __expf(-zv));
        y_p[(size_t)l * DI] = y;
    }
}

// ---------------- launch ----------------
extern "C" void kernel_launch(void* const* d_in, const int* in_sizes, int n_in,
                              void* d_out, int out_size) {
    const float* x      = (const float*)d_in[0];
    const float* W_in   = (const float*)d_in[1];
    const float* conv_w = (const float*)d_in[2];
    const float* conv_b = (const float*)d_in[3];
    const float* W_x    = (const float*)d_in[4];
    const float* W_dt   = (const float*)d_in[5];
    const float* b_dt   = (const float*)d_in[6];
    const float* A_log  = (const float*)d_in[7];
    const float* Dp     = (const float*)d_in[8];
    const float* W_out  = (const float*)d_in[9];
    const float* ln_g   = (const float*)d_in[10];
    const float* ln_b   = (const float*)d_in[11];
    float* out = (float*)d_out;

    float* xn = nullptr; float* xz = nullptr; float* xb = nullptr;
    float* dt = nullptr; float* yy = nullptr;
    cudaGetSymbolAddress((void**)&xn, g_xn);
    cudaGetSymbolAddress((void**)&xz, g_xz);
    cudaGetSymbolAddress((void**)&xb, g_xb);
    cudaGetSymbolAddress((void**)&dt, g_dt);
    cudaGetSymbolAddress((void**)&yy, g_y);

    // 1. LayerNorm
    ln_kernel<<<BL, 256>>>(x, ln_g, ln_b);

    // 2. in-projection (M=4096, N=4096, K=1024)
    gemm_tn<0><<<dim3((2 * DI) / GBN, BL / GBM), 256>>>(xn, W_in, xz, BL, 2 * DI, DM, nullptr);

    // 3. conv + silu
    conv_silu_kernel<<<(BL * DI) / 256, 256>>>(conv_w, conv_b);

    // 4. B/C projection
    xdbl_kernel<<<BL / XT, 256>>>(W_x);

    // 5. dt GEMM + bias + softplus (M=4096, N=2048, K=2048)
    gemm_tn<1><<<dim3(DI / GBN, BL / GBM), 256>>>(xb, W_dt, dt, BL, DI, DI, b_dt);

    // 6. chunked selective scan
    scanA_kernel<<<(BB * CH * DI) / 256, 256>>>(A_log);
    scanC_kernel<<<(BB * DI) / 256, 256>>>();
    scanB_kernel<<<(BB * CH * DI) / 256, 256>>>(A_log, Dp);

    // 7. out-projection + residual (M=4096, N=1024, K=2048)
    gemm_tn<2><<<dim3(DM / GBN, BL / GBM), 256>>>(yy, W_out, out, BL, DM, DI, x);
}

// round 5
// speedup vs baseline: 3.2474x; 1.8971x over previous
#include <cuda_runtime.h>
#include <cuda_bf16.h>
#include <cstdint>

#define BB 2
#define LL 2048
#define DM 1024
#define DI 2048
#define DS 16
#define BL (BB*LL)
#define CH 16
#define CL (LL/CH)

typedef unsigned long long u64;
typedef __nv_bfloat16 bf16;

// ---------------- scratch ----------------
__device__ float g_xz[(size_t)BL * 2 * DI];
__device__ float g_xb[(size_t)BL * DI];
__device__ float g_bc[(size_t)BL * 2 * DS];
__device__ float g_dt[(size_t)BL * DI];
__device__ float g_P [(size_t)BB * CH * DI * DS];
__device__ float g_S [(size_t)BB * CH * DI * DS];
__device__ float g_Hi[(size_t)BB * CH * DI * DS];
__device__ bf16 g_xnh[(size_t)BL * DM];
__device__ bf16 g_xnl[(size_t)BL * DM];
__device__ bf16 g_xbh[(size_t)BL * DI];
__device__ bf16 g_xbl[(size_t)BL * DI];
__device__ bf16 g_yh [(size_t)BL * DI];
__device__ bf16 g_yl [(size_t)BL * DI];
__device__ bf16 g_Winh[(size_t)2 * DI * DM];
__device__ bf16 g_Winl[(size_t)2 * DI * DM];
__device__ bf16 g_Wdth[(size_t)DI * DI];
__device__ bf16 g_Wdtl[(size_t)DI * DI];
__device__ bf16 g_Wouth[(size_t)DM * DI];
__device__ bf16 g_Woutl[(size_t)DM * DI];

// ---------------- helpers ----------------
__device__ __forceinline__ uint32_t smem_u32(const void* p) {
    uint32_t a;
    asm("{ .reg .u64 t; cvta.to.shared.u64 t, %1; cvt.u32.u64 %0, t; }" : "=r"(a) : "l"(p));
    return a;
}
__device__ __forceinline__ void cp16(uint32_t dst, const void* src) {
    asm volatile("cp.async.cg.shared.global [%0], [%1], 16;" :: "r"(dst), "l"(src));
}
#define CP_COMMIT() asm volatile("cp.async.commit_group;" ::: "memory")
#define CP_WAIT0()  asm volatile("cp.async.wait_group 0;" ::: "memory")

__device__ __forceinline__ void ldm_x4(uint32_t* r, uint32_t addr) {
    asm volatile("ldmatrix.sync.aligned.m8n8.x4.shared.b16 {%0,%1,%2,%3}, [%4];"
        : "=r"(r[0]), "=r"(r[1]), "=r"(r[2]), "=r"(r[3]) : "r"(addr));
}
__device__ __forceinline__ void mma16816(float* d, const uint32_t* a, uint32_t b0, uint32_t b1) {
    asm volatile("mma.sync.aligned.m16n8k16.row.col.f32.bf16.bf16.f32 "
        "{%0,%1,%2,%3}, {%4,%5,%6,%7}, {%8,%9}, {%0,%1,%2,%3};"
        : "+f"(d[0]), "+f"(d[1]), "+f"(d[2]), "+f"(d[3])
        : "r"(a[0]), "r"(a[1]), "r"(a[2]), "r"(a[3]), "r"(b0), "r"(b1));
}

__device__ __forceinline__ float warp_sum(float v) {
    #pragma unroll
    for (int o = 16; o > 0; o >>= 1) v += __shfl_xor_sync(0xffffffffu, v, o);
    return v;
}
__device__ __forceinline__ void split_hl(float x, bf16& h, bf16& l) {
    h = __float2bfloat16(x);
    l = __float2bfloat16(x - __bfloat162float(h));
}

// ---------------- weight split ----------------
__global__ __launch_bounds__(256) void split_kernel(const float* __restrict__ src,
                                                    bf16* __restrict__ hi,
                                                    bf16* __restrict__ lo, int n4) {
    int i = blockIdx.x * 256 + threadIdx.x;
    if (i >= n4) return;
    float4 v = ((const float4*)src)[i];
    bf16 h0, l0, h1, l1, h2, l2, h3, l3;
    split_hl(v.x, h0, l0); split_hl(v.y, h1, l1);
    split_hl(v.z, h2, l2); split_hl(v.w, h3, l3);
    __nv_bfloat162* H = (__nv_bfloat162*)(hi) + 2 * i;
    __nv_bfloat162* L = (__nv_bfloat162*)(lo) + 2 * i;
    H[0] = __nv_bfloat162(h0, h1); H[1] = __nv_bfloat162(h2, h3);
    L[0] = __nv_bfloat162(l0, l1); L[1] = __nv_bfloat162(l2, l3);
}

// ---------------- LayerNorm -> bf16 hi/lo ----------------
__global__ __launch_bounds__(256) void ln_kernel(const float* __restrict__ x,
                                                 const float* __restrict__ g,
                                                 const float* __restrict__ b) {
    int t = blockIdx.x;
    int tid = threadIdx.x;
    const float4* row = (const float4*)(x + (size_t)t * DM);
    float4 v = row[tid];
    float s  = v.x + v.y + v.z + v.w;
    float sq = v.x*v.x + v.y*v.y + v.z*v.z + v.w*v.w;
    __shared__ float red[16];
    __shared__ float stats[2];
    s = warp_sum(s); sq = warp_sum(sq);
    int wid = tid >> 5, lid = tid & 31;
    if (lid == 0) { red[wid] = s; red[8 + wid] = sq; }
    __syncthreads();
    if (tid < 32) {
        float ss = (tid < 8) ? red[tid] : 0.f;
        float qq = (tid < 8) ? red[8 + tid] : 0.f;
        ss = warp_sum(ss); qq = warp_sum(qq);
        if (tid == 0) {
            float mu = ss * (1.f / DM);
            float var = qq * (1.f / DM) - mu * mu;
            stats[0] = mu; stats[1] = rsqrtf(var + 1e-5f);
        }
    }
    __syncthreads();
    float mu = stats[0], rstd = stats[1];
    float4 gg = ((const float4*)g)[tid];
    float4 bb = ((const float4*)b)[tid];
    float o0 = (v.x - mu) * rstd * gg.x + bb.x;
    float o1 = (v.y - mu) * rstd * gg.y + bb.y;
    float o2 = (v.z - mu) * rstd * gg.z + bb.z;
    float o3 = (v.w - mu) * rstd * gg.w + bb.w;
    bf16 h0,l0,h1,l1,h2,l2,h3,l3;
    split_hl(o0,h0,l0); split_hl(o1,h1,l1); split_hl(o2,h2,l2); split_hl(o3,h3,l3);
    __nv_bfloat162* H = (__nv_bfloat162*)(g_xnh + (size_t)t * DM) + 2 * tid;
    __nv_bfloat162* L = (__nv_bfloat162*)(g_xnl + (size_t)t * DM) + 2 * tid;
    H[0] = __nv_bfloat162(h0, h1); H[1] = __nv_bfloat162(h2, h3);
    L[0] = __nv_bfloat162(l0, l1); L[1] = __nv_bfloat162(l2, l3);
}

// ---------------- mma.sync bf16 GEMM: C[M,N] = A[M,K]*B[N,K]^T, hi/lo compensated ----------------
// MODE 0: store. MODE 1: softplus(v+bias[n]). MODE 2: v + res[m*N+n].
#define SW 40                        /* bf16 row stride in smem (80 bytes) */
#define TILE_BYTES (128 * SW * 2)    /* 10240 */
#define STAGE_BYTES (4 * TILE_BYTES) /* Ah, Al, Bh, Bl */
#define GEMM_SMEM (2 * STAGE_BYTES)  /* 81920 */

template<int MODE>
__global__ __launch_bounds__(256) void mma_gemm(
    const bf16* __restrict__ Ah, const bf16* __restrict__ Al,
    const bf16* __restrict__ Bh, const bf16* __restrict__ Bl,
    float* __restrict__ C, int M, int N, int K,
    const float* __restrict__ extra)
{
    extern __shared__ __align__(128) char smem[];
    uint32_t sb = smem_u32(smem);
    int tid = threadIdx.x, lane = tid & 31, wid = tid >> 5;
    int m0 = blockIdx.y * 128, n0 = blockIdx.x * 128;
    int wm = (wid & 1) * 64, wn = (wid >> 1) * 32;

    float acc[4][4][4];
    #pragma unroll
    for (int i = 0; i < 4; i++)
        #pragma unroll
        for (int j = 0; j < 4; j++)
            #pragma unroll
            for (int r = 0; r < 4; r++) acc[i][j][r] = 0.f;

    const bf16* pAh = Ah + (size_t)m0 * K;
    const bf16* pAl = Al + (size_t)m0 * K;
    const bf16* pBh = Bh + (size_t)n0 * K;
    const bf16* pBl = Bl + (size_t)n0 * K;

    // loader: 512 16B-chunks per tile, 2 per thread
    int lrow0 = tid >> 2;                 // chunk row for c=0 (0..63)
    int lkc   = tid & 3;                  // 16B chunk within 64B row
    int nk = K / 32;

    auto load_stage = [&](int s, int k0) {
        uint32_t base = sb + s * STAGE_BYTES;
        #pragma unroll
        for (int c = 0; c < 2; c++) {
            int row = lrow0 + c * 64;
            uint32_t so = row * 80 + lkc * 16;
            size_t go = (size_t)row * K + k0 + lkc * 8;
            cp16(base + 0 * TILE_BYTES + so, pAh + go);
            cp16(base + 1 * TILE_BYTES + so, pAl + go);
            cp16(base + 2 * TILE_BYTES + so, pBh + go);
            cp16(base + 3 * TILE_BYTES + so, pBl + go);
        }
    };

    load_stage(0, 0);
    CP_COMMIT();

    for (int kt = 0; kt < nk; kt++) {
        CP_WAIT0();
        __syncthreads();
        if (kt + 1 < nk) { load_stage((kt + 1) & 1, (kt + 1) * 32); CP_COMMIT(); }

        uint32_t base = sb + (kt & 1) * STAGE_BYTES;
        uint32_t frow = lane & 15;
        #pragma unroll
        for (int ks = 0; ks < 2; ks++) {
            uint32_t fcol = ks * 16 + (lane >> 4) * 8;
            uint32_t ah[4][4], al[4][4];
            #pragma unroll
            for (int mi = 0; mi < 4; mi++) {
                uint32_t addr = base + (wm + mi * 16 + frow) * 80 + fcol * 2;
                ldm_x4(ah[mi], addr);
                ldm_x4(al[mi], addr + TILE_BYTES);
            }
            uint32_t bh[2][4], bl[2][4];
            #pragma unroll
            for (int nj = 0; nj < 2; nj++) {
                uint32_t addr = base + 2 * TILE_BYTES + (wn + nj * 16 + frow) * 80 + fcol * 2;
                ldm_x4(bh[nj], addr);
                ldm_x4(bl[nj], addr + TILE_BYTES);
            }
            #pragma unroll
            for (int mi = 0; mi < 4; mi++) {
                #pragma unroll
                for (int nf = 0; nf < 4; nf++) {
                    uint32_t b0h = bh[nf >> 1][nf & 1], b1h = bh[nf >> 1][(nf & 1) + 2];
                    uint32_t b0l = bl[nf >> 1][nf & 1], b1l = bl[nf >> 1][(nf & 1) + 2];
                    mma16816(acc[mi][nf], ah[mi], b0h, b1h);
                    mma16816(acc[mi][nf], ah[mi], b0l, b1l);
                    mma16816(acc[mi][nf], al[mi], b0h, b1h);
                }
            }
        }
    }

    // epilogue
    #pragma unroll
    for (int mi = 0; mi < 4; mi++) {
        int mA = m0 + wm + mi * 16 + (lane >> 2);
        #pragma unroll
        for (int nf = 0; nf < 4; nf++) {
            int n = n0 + wn + nf * 8 + (lane & 3) * 2;
            float v0 = acc[mi][nf][0], v1 = acc[mi][nf][1];
            float v2 = acc[mi][nf][2], v3 = acc[mi][nf][3];
            if (MODE == 1) {
                float b0 = extra[n], b1 = extra[n + 1];
                v0 += b0; v1 += b1; v2 += b0; v3 += b1;
                v0 = (v0 > 20.f) ? v0 : log1pf(__expf(v0));
                v1 = (v1 > 20.f) ? v1 : log1pf(__expf(v1));
                v2 = (v2 > 20.f) ? v2 : log1pf(__expf(v2));
                v3 = (v3 > 20.f) ? v3 : log1pf(__expf(v3));
            } else if (MODE == 2) {
                const float* r0 = extra + (size_t)mA * N + n;
                const float* r1 = extra + (size_t)(mA + 8) * N + n;
                v0 += r0[0]; v1 += r0[1]; v2 += r1[0]; v3 += r1[1];
            }
            float2 p0; p0.x = v0; p0.y = v1;
            float2 p1; p1.x = v2; p1.y = v3;
            *(float2*)(C + (size_t)mA * N + n) = p0;
            *(float2*)(C + (size_t)(mA + 8) * N + n) = p1;
        }
    }
}

// ---------------- conv + silu -> fp32 + bf16 hi/lo ----------------
__global__ __launch_bounds__(256) void conv_silu_kernel(const float* __restrict__ cw,
                                                        const float* __restrict__ cb) {
    int idx = blockIdx.x * blockDim.x + threadIdx.x;
    if (idx >= BL * DI) return;
    int d = idx & (DI - 1);
    int t = idx >> 11;
    int l = t & (LL - 1);
    int bb = t >> 11;
    float w0 = cw[d * 4 + 0], w1 = cw[d * 4 + 1];
    float w2 = cw[d * 4 + 2], w3 = cw[d * 4 + 3];
    const float* base = g_xz + ((size_t)(bb << 11)) * (2 * DI) + d;
    float acc = cb[d];
    if (l >= 3) acc += w0 * base[(size_t)(l - 3) * (2 * DI)];
    if (l >= 2) acc += w1 * base[(size_t)(l - 2) * (2 * DI)];
    if (l >= 1) acc += w2 * base[(size_t)(l - 1) * (2 * DI)];
    acc += w3 * base[(size_t)l * (2 * DI)];
    float s = acc / (1.f + __expf(-acc));
    g_xb[idx] = s;
    bf16 h, lo; split_hl(s, h, lo);
    g_xbh[idx] = h; g_xbl[idx] = lo;
}

// ---------------- B/C projection: 4-way K-split + atomics ----------------
__global__ __launch_bounds__(256) void xdbl_kernel(const float* __restrict__ Wx) {
    __shared__ __align__(16) float sX[16][32 + 4];
    __shared__ __align__(16) float sW[16][32 + 4];
    int tid = threadIdx.x;
    int t0 = (blockIdx.x >> 2) * 32;
    int kbase = (blockIdx.x & 3) * (DI / 4);
    int tx = tid & 31, ty = tid >> 5;
    float acc[4] = {0.f, 0.f, 0.f, 0.f};

    for (int k0 = kbase; k0 < kbase + DI / 4; k0 += 16) {
        int row = (tid & 127) >> 2;
        int kq  = (tid & 3) << 2;
        if (tid < 128) {
            float4 v = *(const float4*)(g_xb + (size_t)(t0 + row) * DI + k0 + kq);
            sX[kq + 0][row] = v.x; sX[kq + 1][row] = v.y;
            sX[kq + 2][row] = v.z; sX[kq + 3][row] = v.w;
        } else {
            float4 v = *(const float4*)(Wx + (size_t)row * DI + k0 + kq);
            sW[kq + 0][row] = v.x; sW[kq + 1][row] = v.y;
            sW[kq + 2][row] = v.z; sW[kq + 3][row] = v.w;
        }
        __syncthreads();
        #pragma unroll
        for (int kk = 0; kk < 16; kk++) {
            float w = sW[kk][tx];
            float4 xv = *(const float4*)&sX[kk][ty * 4];
            acc[0] += xv.x * w; acc[1] += xv.y * w;
            acc[2] += xv.z * w; acc[3] += xv.w * w;
        }
        __syncthreads();
    }
    #pragma unroll
    for (int i = 0; i < 4; i++)
        atomicAdd(&g_bc[(size_t)(t0 + ty * 4 + i) * 32 + tx], acc[i]);
}

// ---------------- chunked selective scan ----------------
__global__ __launch_bounds__(256) void scanA_kernel(const float* __restrict__ A_log) {
    int id = blockIdx.x * 256 + threadIdx.x;
    int d = id & (DI - 1);
    int c = (id >> 11) & (CH - 1);
    int b = id >> 15;

    float Aa[16];
    #pragma unroll
    for (int n = 0; n < 16; n++) Aa[n] = -__expf(A_log[(size_t)d * DS + n]);

    float h[16], P[16];
    #pragma unroll
    for (int n = 0; n < 16; n++) { h[n] = 0.f; P[n] = 1.f; }

    int l0 = c * CL;
    const float* dt_p = g_dt + ((size_t)b * LL + l0) * DI + d;
    const float* xb_p = g_xb + ((size_t)b * LL + l0) * DI + d;
    const float4* bc4 = (const float4*)(g_bc + ((size_t)b * LL + l0) * 32);

    for (int l = 0; l < CL; l++) {
        float dtv = dt_p[(size_t)l * DI];
        float xv  = xb_p[(size_t)l * DI];
        float Bv[16];
        *(float4*)&Bv[0]  = bc4[l * 8 + 0];
        *(float4*)&Bv[4]  = bc4[l * 8 + 1];
        *(float4*)&Bv[8]  = bc4[l * 8 + 2];
        *(float4*)&Bv[12] = bc4[l * 8 + 3];
        float dx = dtv * xv;
        #pragma unroll
        for (int n = 0; n < 16; n++) {
            float ab = __expf(dtv * Aa[n]);
            h[n] = ab * h[n] + dx * Bv[n];
            P[n] *= ab;
        }
    }
    size_t base = (((size_t)b * CH + c) * DI + d) * DS;
    #pragma unroll
    for (int n = 0; n < 16; n += 4) {
        *(float4*)(g_S + base + n) = *(float4*)&h[n];
        *(float4*)(g_P + base + n) = *(float4*)&P[n];
    }
}

__global__ __launch_bounds__(256) void scanC_kernel() {
    int id = blockIdx.x * 256 + threadIdx.x;
    int d = id & (DI - 1);
    int b = id >> 11;
    float h[16];
    #pragma unroll
    for (int n = 0; n < 16; n++) h[n] = 0.f;
    for (int c = 0; c < CH; c++) {
        size_t base = (((size_t)b * CH + c) * DI + d) * DS;
        #pragma unroll
        for (int n = 0; n < 16; n += 4)
            *(float4*)(g_Hi + base + n) = *(float4*)&h[n];
        float P[16], S[16];
        #pragma unroll
        for (int n = 0; n < 16; n += 4) {
            *(float4*)&P[n] = *(const float4*)(g_P + base + n);
            *(float4*)&S[n] = *(const float4*)(g_S + base + n);
        }
        #pragma unroll
        for (int n = 0; n < 16; n++) h[n] = P[n] * h[n] + S[n];
    }
}

__global__ __launch_bounds__(256) void scanB_kernel(const float* __restrict__ A_log,
                                                    const float* __restrict__ Dp) {
    int id = blockIdx.x * 256 + threadIdx.x;
    int d = id & (DI - 1);
    int c = (id >> 11) & (CH - 1);
    int b = id >> 15;

    float Aa[16];
    #pragma unroll
    for (int n = 0; n < 16; n++) Aa[n] = -__expf(A_log[(size_t)d * DS + n]);
    float dpv = Dp[d];

    float h[16];
    size_t hbase = (((size_t)b * CH + c) * DI + d) * DS;
    #pragma unroll
    for (int n = 0; n < 16; n += 4)
        *(float4*)&h[n] = *(const float4*)(g_Hi + hbase + n);

    int l0 = c * CL;
    const float* dt_p = g_dt + ((size_t)b * LL + l0) * DI + d;
    const float* xb_p = g_xb + ((size_t)b * LL + l0) * DI + d;
    const float* z_p  = g_xz + ((size_t)b * LL + l0) * (2 * DI) + DI + d;
    const float4* bc4 = (const float4*)(g_bc + ((size_t)b * LL + l0) * 32);
    bf16* yh_p = g_yh + ((size_t)b * LL + l0) * DI + d;
    bf16* yl_p = g_yl + ((size_t)b * LL + l0) * DI + d;

    for (int l = 0; l < CL; l++) {
        float dtv = dt_p[(size_t)l * DI];
        float xv  = xb_p[(size_t)l * DI];
        float Bv[16], Cv[16];
        *(float4*)&Bv[0]  = bc4[l * 8 + 0];
        *(float4*)&Bv[4]  = bc4[l * 8 + 1];
        *(float4*)&Bv[8]  = bc4[l * 8 + 2];
        *(float4*)&Bv[12] = bc4[l * 8 + 3];
        *(float4*)&Cv[0]  = bc4[l * 8 + 4];
        *(float4*)&Cv[4]  = bc4[l * 8 + 5];
        *(float4*)&Cv[8]  = bc4[l * 8 + 6];
        *(float4*)&Cv[12] = bc4[l * 8 + 7];

        float dx = dtv * xv;
        float y = 0.f;
        #pragma unroll
        for (int n = 0; n < 16; n++) {
            float ab = __expf(dtv * Aa[n]);
            h[n] = ab * h[n] + dx * Bv[n];
            y += h[n] * Cv[n];
        }
        y += dpv * xv;
        float zv = z_p[(size_t)l * (2 * DI)];
        y *= zv / (1.f + __expf(-zv));
        bf16 yh, yl; split_hl(y, yh, yl);
        yh_p[(size_t)l * DI] = yh;
        yl_p[(size_t)l * DI] = yl;
    }
}

// ---------------- launch ----------------
extern "C" void kernel_launch(void* const* d_in, const int* in_sizes, int n_in,
                              void* d_out, int out_size) {
    const float* x      = (const float*)d_in[0];
    const float* W_in   = (const float*)d_in[1];
    const float* conv_w = (const float*)d_in[2];
    const float* conv_b = (const float*)d_in[3];
    const float* W_x    = (const float*)d_in[4];
    const float* W_dt   = (const float*)d_in[5];
    const float* b_dt   = (const float*)d_in[6];
    const float* A_log  = (const float*)d_in[7];
    const float* Dp     = (const float*)d_in[8];
    const float* W_out  = (const float*)d_in[9];
    const float* ln_g   = (const float*)d_in[10];
    const float* ln_b   = (const float*)d_in[11];
    float* out = (float*)d_out;

    float *xz, *dt, *bc;
    bf16 *xnh, *xnl, *xbh, *xbl, *yh, *yl;
    bf16 *winh, *winl, *wdth, *wdtl, *wouth, *woutl;
    cudaGetSymbolAddress((void**)&xz, g_xz);
    cudaGetSymbolAddress((void**)&dt, g_dt);
    cudaGetSymbolAddress((void**)&bc, g_bc);
    cudaGetSymbolAddress((void**)&xnh, g_xnh);
    cudaGetSymbolAddress((void**)&xnl, g_xnl);
    cudaGetSymbolAddress((void**)&xbh, g_xbh);
    cudaGetSymbolAddress((void**)&xbl, g_xbl);
    cudaGetSymbolAddress((void**)&yh, g_yh);
    cudaGetSymbolAddress((void**)&yl, g_yl);
    cudaGetSymbolAddress((void**)&winh, g_Winh);
    cudaGetSymbolAddress((void**)&winl, g_Winl);
    cudaGetSymbolAddress((void**)&wdth, g_Wdth);
    cudaGetSymbolAddress((void**)&wdtl, g_Wdtl);
    cudaGetSymbolAddress((void**)&wouth, g_Wouth);
    cudaGetSymbolAddress((void**)&woutl, g_Woutl);

    cudaFuncSetAttribute(mma_gemm<0>, cudaFuncAttributeMaxDynamicSharedMemorySize, GEMM_SMEM);
    cudaFuncSetAttribute(mma_gemm<1>, cudaFuncAttributeMaxDynamicSharedMemorySize, GEMM_SMEM);
    cudaFuncSetAttribute(mma_gemm<2>, cudaFuncAttributeMaxDynamicSharedMemorySize, GEMM_SMEM);

    // weight splits
    split_kernel<<<(2 * DI * DM / 4 + 255) / 256, 256>>>(W_in, winh, winl, 2 * DI * DM / 4);
    split_kernel<<<(DI * DI / 4 + 255) / 256, 256>>>(W_dt, wdth, wdtl, DI * DI / 4);
    split_kernel<<<(DM * DI / 4 + 255) / 256, 256>>>(W_out, wouth, woutl, DM * DI / 4);

    // 1. LayerNorm -> xn hi/lo
    ln_kernel<<<BL, 256>>>(x, ln_g, ln_b);

    // 2. in-projection (M=4096, N=4096, K=1024)
    mma_gemm<0><<<dim3((2 * DI) / 128, BL / 128), 256, GEMM_SMEM>>>(
        xnh, xnl, winh, winl, xz, BL, 2 * DI, DM, nullptr);

    // 3. conv + silu
    conv_silu_kernel<<<(BL * DI) / 256, 256>>>(conv_w, conv_b);

    // 4. B/C projection
    cudaMemsetAsync(bc, 0, (size_t)BL * 32 * sizeof(float));
    xdbl_kernel<<<(BL / 32) * 4, 256>>>(W_x);

    // 5. dt GEMM + softplus (M=4096, N=2048, K=2048)
    mma_gemm<1><<<dim3(DI / 128, BL / 128), 256, GEMM_SMEM>>>(
        xbh, xbl, wdth, wdtl, dt, BL, DI, DI, b_dt);

    // 6. chunked scan
    scanA_kernel<<<(BB * CH * DI) / 256, 256>>>(A_log);
    scanC_kernel<<<(BB * DI) / 256, 256>>>();
    scanB_kernel<<<(BB * CH * DI) / 256, 256>>>(A_log, Dp);

    // 7. out-projection + residual (M=4096, N=1024, K=2048)
    mma_gemm<2><<<dim3(DM / 128, BL / 128), 256, GEMM_SMEM>>>(
        yh, yl, wouth, woutl, out, BL, DM, DI, x);
}

// round 6
// speedup vs baseline: 5.4889x; 1.6902x over previous
#include <cuda_runtime.h>
#include <cuda_fp16.h>
#include <cstdint>

#define BB 2
#define LL 2048
#define DM 1024
#define DI 2048
#define DS 16
#define BL (BB*LL)
#define CH 16
#define CL (LL/CH)

typedef unsigned long long u64;

// ---------------- scratch ----------------
__device__ float g_xz[(size_t)BL * 2 * DI];
__device__ float g_xb[(size_t)BL * DI];
__device__ float g_bc[(size_t)BL * 2 * DS];
__device__ float g_dt[(size_t)BL * DI];
__device__ float g_P [(size_t)BB * CH * DI * DS];
__device__ float g_S [(size_t)BB * CH * DI * DS];
__device__ float g_Hi[(size_t)BB * CH * DI * DS];
__device__ __half g_xnh[(size_t)BL * DM];
__device__ __half g_xbh[(size_t)BL * DI];
__device__ __half g_yh [(size_t)BL * DI];
__device__ __half g_Winh[(size_t)2 * DI * DM];
__device__ __half g_Wdth[(size_t)DI * DI];
__device__ __half g_Wouth[(size_t)DM * DI];

// ---------------- helpers ----------------
__device__ __forceinline__ uint32_t smem_u32(const void* p) {
    uint32_t a;
    asm("{ .reg .u64 t; cvta.to.shared.u64 t, %1; cvt.u32.u64 %0, t; }" : "=r"(a) : "l"(p));
    return a;
}
__device__ __forceinline__ void cp16(uint32_t dst, const void* src) {
    asm volatile("cp.async.cg.shared.global [%0], [%1], 16;" :: "r"(dst), "l"(src));
}
#define CP_COMMIT() asm volatile("cp.async.commit_group;" ::: "memory")
#define CP_WAIT1()  asm volatile("cp.async.wait_group 1;" ::: "memory")
#define CP_WAIT0()  asm volatile("cp.async.wait_group 0;" ::: "memory")

__device__ __forceinline__ void ldm_x4(uint32_t* r, uint32_t addr) {
    asm volatile("ldmatrix.sync.aligned.m8n8.x4.shared.b16 {%0,%1,%2,%3}, [%4];"
        : "=r"(r[0]), "=r"(r[1]), "=r"(r[2]), "=r"(r[3]) : "r"(addr));
}
__device__ __forceinline__ void mma16816(float* d, const uint32_t* a, uint32_t b0, uint32_t b1) {
    asm volatile("mma.sync.aligned.m16n8k16.row.col.f32.f16.f16.f32 "
        "{%0,%1,%2,%3}, {%4,%5,%6,%7}, {%8,%9}, {%0,%1,%2,%3};"
        : "+f"(d[0]), "+f"(d[1]), "+f"(d[2]), "+f"(d[3])
        : "r"(a[0]), "r"(a[1]), "r"(a[2]), "r"(a[3]), "r"(b0), "r"(b1));
}

__device__ __forceinline__ float warp_sum(float v) {
    #pragma unroll
    for (int o = 16; o > 0; o >>= 1) v += __shfl_xor_sync(0xffffffffu, v, o);
    return v;
}

// ---------------- weight convert fp32 -> fp16 ----------------
__global__ __launch_bounds__(256) void split_kernel(const float* __restrict__ src,
                                                    __half* __restrict__ hi, int n4) {
    int i = blockIdx.x * 256 + threadIdx.x;
    if (i >= n4) return;
    float4 v = ((const float4*)src)[i];
    __half2* H = (__half2*)(hi) + 2 * i;
    H[0] = __half2(__float2half_rn(v.x), __float2half_rn(v.y));
    H[1] = __half2(__float2half_rn(v.z), __float2half_rn(v.w));
}

// ---------------- LayerNorm -> fp16 ----------------
__global__ __launch_bounds__(256) void ln_kernel(const float* __restrict__ x,
                                                 const float* __restrict__ g,
                                                 const float* __restrict__ b) {
    int t = blockIdx.x;
    int tid = threadIdx.x;
    const float4* row = (const float4*)(x + (size_t)t * DM);
    float4 v = row[tid];
    float s  = v.x + v.y + v.z + v.w;
    float sq = v.x*v.x + v.y*v.y + v.z*v.z + v.w*v.w;
    __shared__ float red[16];
    __shared__ float stats[2];
    s = warp_sum(s); sq = warp_sum(sq);
    int wid = tid >> 5, lid = tid & 31;
    if (lid == 0) { red[wid] = s; red[8 + wid] = sq; }
    __syncthreads();
    if (tid < 32) {
        float ss = (tid < 8) ? red[tid] : 0.f;
        float qq = (tid < 8) ? red[8 + tid] : 0.f;
        ss = warp_sum(ss); qq = warp_sum(qq);
        if (tid == 0) {
            float mu = ss * (1.f / DM);
            float var = qq * (1.f / DM) - mu * mu;
            stats[0] = mu; stats[1] = rsqrtf(var + 1e-5f);
        }
    }
    __syncthreads();
    float mu = stats[0], rstd = stats[1];
    float4 gg = ((const float4*)g)[tid];
    float4 bb = ((const float4*)b)[tid];
    float o0 = (v.x - mu) * rstd * gg.x + bb.x;
    float o1 = (v.y - mu) * rstd * gg.y + bb.y;
    float o2 = (v.z - mu) * rstd * gg.z + bb.z;
    float o3 = (v.w - mu) * rstd * gg.w + bb.w;
    __half2* H = (__half2*)(g_xnh + (size_t)t * DM) + 2 * tid;
    H[0] = __half2(__float2half_rn(o0), __float2half_rn(o1));
    H[1] = __half2(__float2half_rn(o2), __float2half_rn(o3));
}

// ---------------- mma.sync fp16 GEMM: C[M,N] = A[M,K]*B[N,K]^T ----------------
// MODE 0: store. MODE 1: softplus(v+bias[n]). MODE 2: v + res[m*N+n].
#define SW 40                        /* fp16 row stride in smem (80 bytes) */
#define TILE_BYTES (128 * SW * 2)    /* 10240 */
#define STAGE_BYTES (2 * TILE_BYTES) /* A, B */
#define GEMM_SMEM (3 * STAGE_BYTES)  /* 61440 */

template<int MODE>
__global__ __launch_bounds__(256) void mma_gemm(
    const __half* __restrict__ A, const __half* __restrict__ B,
    float* __restrict__ C, int M, int N, int K,
    const float* __restrict__ extra)
{
    extern __shared__ __align__(128) char smem[];
    uint32_t sb = smem_u32(smem);
    int tid = threadIdx.x, lane = tid & 31, wid = tid >> 5;
    int m0 = blockIdx.y * 128, n0 = blockIdx.x * 128;
    int wm = (wid & 1) * 64, wn = (wid >> 1) * 32;

    float acc[4][4][4];
    #pragma unroll
    for (int i = 0; i < 4; i++)
        #pragma unroll
        for (int j = 0; j < 4; j++)
            #pragma unroll
            for (int r = 0; r < 4; r++) acc[i][j][r] = 0.f;

    const __half* pA = A + (size_t)m0 * K;
    const __half* pB = B + (size_t)n0 * K;

    int lrow0 = tid >> 2;
    int lkc   = tid & 3;
    int nk = K / 32;

    auto load_stage = [&](int s, int k0) {
        uint32_t base = sb + s * STAGE_BYTES;
        #pragma unroll
        for (int c = 0; c < 2; c++) {
            int row = lrow0 + c * 64;
            uint32_t so = row * 80 + lkc * 16;
            size_t go = (size_t)row * K + k0 + lkc * 8;
            cp16(base + 0 * TILE_BYTES + so, pA + go);
            cp16(base + 1 * TILE_BYTES + so, pB + go);
        }
    };

    load_stage(0, 0);
    CP_COMMIT();
    load_stage(1, 32);
    CP_COMMIT();

    int stage = 0;
    for (int kt = 0; kt < nk; kt++) {
        CP_WAIT1();
        __syncthreads();
        if (kt + 2 < nk) {
            int s2 = stage + 2; if (s2 >= 3) s2 -= 3;
            load_stage(s2, (kt + 2) * 32);
            CP_COMMIT();
        } else {
            // keep group accounting uniform
            CP_COMMIT();
        }

        uint32_t base = sb + stage * STAGE_BYTES;
        uint32_t frow = lane & 15;
        #pragma unroll
        for (int ks = 0; ks < 2; ks++) {
            uint32_t fcol = ks * 16 + (lane >> 4) * 8;
            uint32_t a[4][4];
            #pragma unroll
            for (int mi = 0; mi < 4; mi++) {
                uint32_t addr = base + (wm + mi * 16 + frow) * 80 + fcol * 2;
                ldm_x4(a[mi], addr);
            }
            uint32_t b[2][4];
            #pragma unroll
            for (int nj = 0; nj < 2; nj++) {
                uint32_t addr = base + TILE_BYTES + (wn + nj * 16 + frow) * 80 + fcol * 2;
                ldm_x4(b[nj], addr);
            }
            #pragma unroll
            for (int mi = 0; mi < 4; mi++) {
                #pragma unroll
                for (int nf = 0; nf < 4; nf++) {
                    uint32_t b0 = b[nf >> 1][nf & 1], b1 = b[nf >> 1][(nf & 1) + 2];
                    mma16816(acc[mi][nf], a[mi], b0, b1);
                }
            }
        }
        stage++; if (stage >= 3) stage = 0;
        __syncthreads();
    }

    // epilogue
    #pragma unroll
    for (int mi = 0; mi < 4; mi++) {
        int mA = m0 + wm + mi * 16 + (lane >> 2);
        #pragma unroll
        for (int nf = 0; nf < 4; nf++) {
            int n = n0 + wn + nf * 8 + (lane & 3) * 2;
            float v0 = acc[mi][nf][0], v1 = acc[mi][nf][1];
            float v2 = acc[mi][nf][2], v3 = acc[mi][nf][3];
            if (MODE == 1) {
                float b0 = extra[n], b1 = extra[n + 1];
                v0 += b0; v1 += b1; v2 += b0; v3 += b1;
                v0 = (v0 > 20.f) ? v0 : log1pf(__expf(v0));
                v1 = (v1 > 20.f) ? v1 : log1pf(__expf(v1));
                v2 = (v2 > 20.f) ? v2 : log1pf(__expf(v2));
                v3 = (v3 > 20.f) ? v3 : log1pf(__expf(v3));
            } else if (MODE == 2) {
                const float* r0 = extra + (size_t)mA * N + n;
                const float* r1 = extra + (size_t)(mA + 8) * N + n;
                v0 += r0[0]; v1 += r0[1]; v2 += r1[0]; v3 += r1[1];
            }
            float2 p0; p0.x = v0; p0.y = v1;
            float2 p1; p1.x = v2; p1.y = v3;
            *(float2*)(C + (size_t)mA * N + n) = p0;
            *(float2*)(C + (size_t)(mA + 8) * N + n) = p1;
        }
    }
}

// ---------------- conv + silu -> fp32 + fp16 ----------------
__global__ __launch_bounds__(256) void conv_silu_kernel(const float* __restrict__ cw,
                                                        const float* __restrict__ cb) {
    int idx = blockIdx.x * blockDim.x + threadIdx.x;
    if (idx >= BL * DI) return;
    int d = idx & (DI - 1);
    int t = idx >> 11;
    int l = t & (LL - 1);
    int bb = t >> 11;
    float w0 = cw[d * 4 + 0], w1 = cw[d * 4 + 1];
    float w2 = cw[d * 4 + 2], w3 = cw[d * 4 + 3];
    const float* base = g_xz + ((size_t)(bb << 11)) * (2 * DI) + d;
    float acc = cb[d];
    if (l >= 3) acc += w0 * base[(size_t)(l - 3) * (2 * DI)];
    if (l >= 2) acc += w1 * base[(size_t)(l - 2) * (2 * DI)];
    if (l >= 1) acc += w2 * base[(size_t)(l - 1) * (2 * DI)];
    acc += w3 * base[(size_t)l * (2 * DI)];
    float s = acc / (1.f + __expf(-acc));
    g_xb[idx] = s;
    g_xbh[idx] = __float2half_rn(s);
}

// ---------------- B/C projection: 4-way K-split + atomics ----------------
__global__ __launch_bounds__(256) void xdbl_kernel(const float* __restrict__ Wx) {
    __shared__ __align__(16) float sX[16][32 + 4];
    __shared__ __align__(16) float sW[16][32 + 4];
    int tid = threadIdx.x;
    int t0 = (blockIdx.x >> 2) * 32;
    int kbase = (blockIdx.x & 3) * (DI / 4);
    int tx = tid & 31, ty = tid >> 5;
    float acc[4] = {0.f, 0.f, 0.f, 0.f};

    for (int k0 = kbase; k0 < kbase + DI / 4; k0 += 16) {
        int row = (tid & 127) >> 2;
        int kq  = (tid & 3) << 2;
        if (tid < 128) {
            float4 v = *(const float4*)(g_xb + (size_t)(t0 + row) * DI + k0 + kq);
            sX[kq + 0][row] = v.x; sX[kq + 1][row] = v.y;
            sX[kq + 2][row] = v.z; sX[kq + 3][row] = v.w;
        } else {
            float4 v = *(const float4*)(Wx + (size_t)row * DI + k0 + kq);
            sW[kq + 0][row] = v.x; sW[kq + 1][row] = v.y;
            sW[kq + 2][row] = v.z; sW[kq + 3][row] = v.w;
        }
        __syncthreads();
        #pragma unroll
        for (int kk = 0; kk < 16; kk++) {
            float w = sW[kk][tx];
            float4 xv = *(const float4*)&sX[kk][ty * 4];
            acc[0] += xv.x * w; acc[1] += xv.y * w;
            acc[2] += xv.z * w; acc[3] += xv.w * w;
        }
        __syncthreads();
    }
    #pragma unroll
    for (int i = 0; i < 4; i++)
        atomicAdd(&g_bc[(size_t)(t0 + ty * 4 + i) * 32 + tx], acc[i]);
}

// ---------------- chunked selective scan ----------------
__global__ __launch_bounds__(256) void scanA_kernel(const float* __restrict__ A_log) {
    int id = blockIdx.x * 256 + threadIdx.x;
    int d = id & (DI - 1);
    int c = (id >> 11) & (CH - 1);
    int b = id >> 15;

    float Aa[16];
    #pragma unroll
    for (int n = 0; n < 16; n++) Aa[n] = -__expf(A_log[(size_t)d * DS + n]);

    float h[16], P[16];
    #pragma unroll
    for (int n = 0; n < 16; n++) { h[n] = 0.f; P[n] = 1.f; }

    int l0 = c * CL;
    const float* dt_p = g_dt + ((size_t)b * LL + l0) * DI + d;
    const float* xb_p = g_xb + ((size_t)b * LL + l0) * DI + d;
    const float4* bc4 = (const float4*)(g_bc + ((size_t)b * LL + l0) * 32);

    for (int l = 0; l < CL; l++) {
        float dtv = dt_p[(size_t)l * DI];
        float xv  = xb_p[(size_t)l * DI];
        float Bv[16];
        *(float4*)&Bv[0]  = bc4[l * 8 + 0];
        *(float4*)&Bv[4]  = bc4[l * 8 + 1];
        *(float4*)&Bv[8]  = bc4[l * 8 + 2];
        *(float4*)&Bv[12] = bc4[l * 8 + 3];
        float dx = dtv * xv;
        #pragma unroll
        for (int n = 0; n < 16; n++) {
            float ab = __expf(dtv * Aa[n]);
            h[n] = ab * h[n] + dx * Bv[n];
            P[n] *= ab;
        }
    }
    size_t base = (((size_t)b * CH + c) * DI + d) * DS;
    #pragma unroll
    for (int n = 0; n < 16; n += 4) {
        *(float4*)(g_S + base + n) = *(float4*)&h[n];
        *(float4*)(g_P + base + n) = *(float4*)&P[n];
    }
}

__global__ __launch_bounds__(256) void scanC_kernel() {
    int id = blockIdx.x * 256 + threadIdx.x;
    int d = id & (DI - 1);
    int b = id >> 11;
    float h[16];
    #pragma unroll
    for (int n = 0; n < 16; n++) h[n] = 0.f;
    for (int c = 0; c < CH; c++) {
        size_t base = (((size_t)b * CH + c) * DI + d) * DS;
        #pragma unroll
        for (int n = 0; n < 16; n += 4)
            *(float4*)(g_Hi + base + n) = *(float4*)&h[n];
        float P[16], S[16];
        #pragma unroll
        for (int n = 0; n < 16; n += 4) {
            *(float4*)&P[n] = *(const float4*)(g_P + base + n);
            *(float4*)&S[n] = *(const float4*)(g_S + base + n);
        }
        #pragma unroll
        for (int n = 0; n < 16; n++) h[n] = P[n] * h[n] + S[n];
    }
}

__global__ __launch_bounds__(256) void scanB_kernel(const float* __restrict__ A_log,
                                                    const float* __restrict__ Dp) {
    int id = blockIdx.x * 256 + threadIdx.x;
    int d = id & (DI - 1);
    int c = (id >> 11) & (CH - 1);
    int b = id >> 15;

    float Aa[16];
    #pragma unroll
    for (int n = 0; n < 16; n++) Aa[n] = -__expf(A_log[(size_t)d * DS + n]);
    float dpv = Dp[d];

    float h[16];
    size_t hbase = (((size_t)b * CH + c) * DI + d) * DS;
    #pragma unroll
    for (int n = 0; n < 16; n += 4)
        *(float4*)&h[n] = *(const float4*)(g_Hi + hbase + n);

    int l0 = c * CL;
    const float* dt_p = g_dt + ((size_t)b * LL + l0) * DI + d;
    const float* xb_p = g_xb + ((size_t)b * LL + l0) * DI + d;
    const float* z_p  = g_xz + ((size_t)b * LL + l0) * (2 * DI) + DI + d;
    const float4* bc4 = (const float4*)(g_bc + ((size_t)b * LL + l0) * 32);
    __half* yh_p = g_yh + ((size_t)b * LL + l0) * DI + d;

    for (int l = 0; l < CL; l++) {
        float dtv = dt_p[(size_t)l * DI];
        float xv  = xb_p[(size_t)l * DI];
        float Bv[16], Cv[16];
        *(float4*)&Bv[0]  = bc4[l * 8 + 0];
        *(float4*)&Bv[4]  = bc4[l * 8 + 1];
        *(float4*)&Bv[8]  = bc4[l * 8 + 2];
        *(float4*)&Bv[12] = bc4[l * 8 + 3];
        *(float4*)&Cv[0]  = bc4[l * 8 + 4];
        *(float4*)&Cv[4]  = bc4[l * 8 + 5];
        *(float4*)&Cv[8]  = bc4[l * 8 + 6];
        *(float4*)&Cv[12] = bc4[l * 8 + 7];

        float dx = dtv * xv;
        float y = 0.f;
        #pragma unroll
        for (int n = 0; n < 16; n++) {
            float ab = __expf(dtv * Aa[n]);
            h[n] = ab * h[n] + dx * Bv[n];
            y += h[n] * Cv[n];
        }
        y += dpv * xv;
        float zv = z_p[(size_t)l * (2 * DI)];
        y *= zv / (1.f + __expf(-zv));
        yh_p[(size_t)l * DI] = __float2half_rn(y);
    }
}

// ---------------- launch ----------------
extern "C" void kernel_launch(void* const* d_in, const int* in_sizes, int n_in,
                              void* d_out, int out_size) {
    const float* x      = (const float*)d_in[0];
    const float* W_in   = (const float*)d_in[1];
    const float* conv_w = (const float*)d_in[2];
    const float* conv_b = (const float*)d_in[3];
    const float* W_x    = (const float*)d_in[4];
    const float* W_dt   = (const float*)d_in[5];
    const float* b_dt   = (const float*)d_in[6];
    const float* A_log  = (const float*)d_in[7];
    const float* Dp     = (const float*)d_in[8];
    const float* W_out  = (const float*)d_in[9];
    const float* ln_g   = (const float*)d_in[10];
    const float* ln_b   = (const float*)d_in[11];
    float* out = (float*)d_out;

    float *xz, *dt, *bc;
    __half *xnh, *xbh, *yh, *winh, *wdth, *wouth;
    cudaGetSymbolAddress((void**)&xz, g_xz);
    cudaGetSymbolAddress((void**)&dt, g_dt);
    cudaGetSymbolAddress((void**)&bc, g_bc);
    cudaGetSymbolAddress((void**)&xnh, g_xnh);
    cudaGetSymbolAddress((void**)&xbh, g_xbh);
    cudaGetSymbolAddress((void**)&yh, g_yh);
    cudaGetSymbolAddress((void**)&winh, g_Winh);
    cudaGetSymbolAddress((void**)&wdth, g_Wdth);
    cudaGetSymbolAddress((void**)&wouth, g_Wouth);

    cudaFuncSetAttribute(mma_gemm<0>, cudaFuncAttributeMaxDynamicSharedMemorySize, GEMM_SMEM);
    cudaFuncSetAttribute(mma_gemm<1>, cudaFuncAttributeMaxDynamicSharedMemorySize, GEMM_SMEM);
    cudaFuncSetAttribute(mma_gemm<2>, cudaFuncAttributeMaxDynamicSharedMemorySize, GEMM_SMEM);

    // weight converts
    split_kernel<<<(2 * DI * DM / 4 + 255) / 256, 256>>>(W_in, winh, 2 * DI * DM / 4);
    split_kernel<<<(DI * DI / 4 + 255) / 256, 256>>>(W_dt, wdth, DI * DI / 4);
    split_kernel<<<(DM * DI / 4 + 255) / 256, 256>>>(W_out, wouth, DM * DI / 4);

    // 1. LayerNorm -> fp16
    ln_kernel<<<BL, 256>>>(x, ln_g, ln_b);

    // 2. in-projection (M=4096, N=4096, K=1024)
    mma_gemm<0><<<dim3((2 * DI) / 128, BL / 128), 256, GEMM_SMEM>>>(
        xnh, winh, xz, BL, 2 * DI, DM, nullptr);

    // 3. conv + silu
    conv_silu_kernel<<<(BL * DI) / 256, 256>>>(conv_w, conv_b);

    // 4. B/C projection
    cudaMemsetAsync(bc, 0, (size_t)BL * 32 * sizeof(float));
    xdbl_kernel<<<(BL / 32) * 4, 256>>>(W_x);

    // 5. dt GEMM + softplus (M=4096, N=2048, K=2048)
    mma_gemm<1><<<dim3(DI / 128, BL / 128), 256, GEMM_SMEM>>>(
        xbh, wdth, dt, BL, DI, DI, b_dt);

    // 6. chunked scan
    scanA_kernel<<<(BB * CH * DI) / 256, 256>>>(A_log);
    scanC_kernel<<<(BB * DI) / 256, 256>>>();
    scanB_kernel<<<(BB * CH * DI) / 256, 256>>>(A_log, Dp);

    // 7. out-projection + residual (M=4096, N=1024, K=2048)
    mma_gemm<2><<<dim3(DM / 128, BL / 128), 256, GEMM_SMEM>>>(
        yh, wouth, out, BL, DM, DI, x);
}